// round 1
// baseline (speedup 1.0000x reference)
#include <cuda_runtime.h>

// Problem constants
#define B_   64
#define N_   2048
#define J_   32
#define D_   16
#define E_   16
#define JD_  512          // J*D
#define EPS_ 1e-8f

// Scratch (device globals: allocation-free rule)
__device__ float g_u[(size_t)B_ * N_ * JD_];   // 268 MB prediction vectors u[b][i][j*16+d]
__device__ float g_s[3][B_ * JD_];             // s1, s2, s3 accumulators
__device__ float g_v[2][B_ * JD_];             // v1, (v1+v2)

// ---------------------------------------------------------------------------
// Zero the s accumulators (graph replays require re-zeroing every launch)
// ---------------------------------------------------------------------------
__global__ void k_zero() {
    int idx = blockIdx.x * blockDim.x + threadIdx.x;     // 96*1024 = 98304 = 3*64*512
    ((float*)g_s)[idx] = 0.0f;
}

// ---------------------------------------------------------------------------
// Compute u[b,i,j,d] = sum_e W[i,j,d,e] * x[b,i,e]
// One CTA per i. 256 threads; thread t owns jd = t and jd = t+256, W rows in
// registers, x for all 64 b staged in smem (broadcast reads).
// ---------------------------------------------------------------------------
__global__ __launch_bounds__(256) void k_u(const float* __restrict__ x,
                                           const float* __restrict__ w) {
    const int i = blockIdx.x;
    const int t = threadIdx.x;

    __shared__ float4 xs[B_][4];   // x[b][e] as 4 float4 per b
    for (int idx = t; idx < B_ * 4; idx += 256) {
        int b = idx >> 2, q = idx & 3;
        xs[b][q] = *(const float4*)(x + ((size_t)b * N_ + i) * E_ + q * 4);
    }

    const float* wp = w + (size_t)i * JD_ * E_;
    float w0[16], w1[16];
    {
        const float4* p0 = (const float4*)(wp + t * E_);
        const float4* p1 = (const float4*)(wp + (t + 256) * E_);
#pragma unroll
        for (int q = 0; q < 4; q++) {
            float4 a = p0[q];
            w0[q*4+0] = a.x; w0[q*4+1] = a.y; w0[q*4+2] = a.z; w0[q*4+3] = a.w;
            float4 c = p1[q];
            w1[q*4+0] = c.x; w1[q*4+1] = c.y; w1[q*4+2] = c.z; w1[q*4+3] = c.w;
        }
    }
    __syncthreads();

#pragma unroll 4
    for (int b = 0; b < B_; b++) {
        float a0 = 0.f, a1 = 0.f;
#pragma unroll
        for (int q = 0; q < 4; q++) {
            float4 xv = xs[b][q];
            a0 += w0[q*4+0]*xv.x + w0[q*4+1]*xv.y + w0[q*4+2]*xv.z + w0[q*4+3]*xv.w;
            a1 += w1[q*4+0]*xv.x + w1[q*4+1]*xv.y + w1[q*4+2]*xv.z + w1[q*4+3]*xv.w;
        }
        float* up = g_u + ((size_t)b * N_ + i) * JD_;
        up[t]       = a0;
        up[t + 256] = a1;
    }
}

// ---------------------------------------------------------------------------
// Routing sweep: for each (b,i):
//   if vIdx >= 0:  bl[j] = sum_d u[j,d] * v[b,j,d];  c = softmax_j(bl)
//   else:          c = 1/32  (softmax of zero logits, iteration 1)
//   s[sIdx][b,j,d] += c[j] * u[j,d]   (summed over i)
// Grid (16 i-chunks, 64 b), 256 threads = 8 warps, warp handles 16 i's,
// lane = j. Per-warp partials staged in smem, single atomicAdd per output.
// ---------------------------------------------------------------------------
__global__ __launch_bounds__(256) void k_pass(int vIdx, int sIdx) {
    const int b    = blockIdx.y;
    const int ic   = blockIdx.x;
    const int t    = threadIdx.x;
    const int warp = t >> 5;
    const int j    = t & 31;

    __shared__ float vs[JD_];
    __shared__ float ss[8][JD_];   // per-warp partials, layout [warp][d*32 + j]

    if (vIdx >= 0) {
        for (int idx = t; idx < JD_; idx += 256)
            vs[idx] = g_v[vIdx][b * JD_ + idx];
    }
    __syncthreads();

    float vj[16];
    if (vIdx >= 0) {
#pragma unroll
        for (int d = 0; d < 16; d++) vj[d] = vs[j * 16 + d];
    }

    float acc[16];
#pragma unroll
    for (int d = 0; d < 16; d++) acc[d] = 0.f;

    const int ibase = ic * 128 + warp * 16;
    for (int k = 0; k < 16; k++) {
        const int i = ibase + k;
        const float4* up = (const float4*)(g_u + ((size_t)b * N_ + i) * JD_ + j * 16);
        float u[16];
#pragma unroll
        for (int q = 0; q < 4; q++) {
            float4 uu = up[q];
            u[q*4+0] = uu.x; u[q*4+1] = uu.y; u[q*4+2] = uu.z; u[q*4+3] = uu.w;
        }

        float c;
        if (vIdx >= 0) {
            float bl = 0.f;
#pragma unroll
            for (int d = 0; d < 16; d++) bl += u[d] * vj[d];
            // softmax over the 32 j-lanes
            float m = bl;
#pragma unroll
            for (int o = 16; o > 0; o >>= 1)
                m = fmaxf(m, __shfl_xor_sync(0xffffffffu, m, o));
            float ex = __expf(bl - m);
            float sum = ex;
#pragma unroll
            for (int o = 16; o > 0; o >>= 1)
                sum += __shfl_xor_sync(0xffffffffu, sum, o);
            c = ex / sum;
        } else {
            c = 1.0f / 32.0f;
        }
#pragma unroll
        for (int d = 0; d < 16; d++) acc[d] += c * u[d];
    }

    // stage per-warp partials (conflict-free: lane j writes d*32+j)
#pragma unroll
    for (int d = 0; d < 16; d++) ss[warp][d * 32 + j] = acc[d];
    __syncthreads();

    // reduce 8 warps -> one atomicAdd per output element
    for (int idx = t; idx < JD_; idx += 256) {
        int d = idx >> 5, jj = idx & 31;
        float r = 0.f;
#pragma unroll
        for (int wi = 0; wi < 8; wi++) r += ss[wi][idx];
        atomicAdd(&g_s[sIdx][b * JD_ + jj * 16 + d], r);
    }
}

// ---------------------------------------------------------------------------
// Squash over the capsule axis J (per (b,d)): sq_d = sum_j s[j,d]^2
// mode 0: g_v[0] = squash(s)              (v1)
// mode 1: g_v[1] = squash(s) + g_v[0]     (v1 + v2, additive logits)
// ---------------------------------------------------------------------------
__global__ void k_squash_j(int sIdx, int mode) {
    const int b = blockIdx.x;
    const int t = threadIdx.x;               // t = j*16 + d
    __shared__ float sq[16];
    if (t < 16) sq[t] = 0.f;
    __syncthreads();
    float s = g_s[sIdx][b * JD_ + t];
    atomicAdd(&sq[t & 15], s * s);
    __syncthreads();
    float q = sq[t & 15];
    float v = s * (q / (1.f + q)) * rsqrtf(q + EPS_);
    if (mode == 0) g_v[0][b * JD_ + t] = v;
    else           g_v[1][b * JD_ + t] = v + g_v[0][b * JD_ + t];
}

// ---------------------------------------------------------------------------
// Final squash over D (per (b,j)): out = s * sq/(1+sq) / sqrt(sq+eps)
// ---------------------------------------------------------------------------
__global__ void k_final(float* __restrict__ out) {
    const int b = blockIdx.x;
    const int t = threadIdx.x;               // t = j*16 + d
    float s = g_s[2][b * JD_ + t];
    float q = s * s;
#pragma unroll
    for (int o = 1; o < 16; o <<= 1)         // groups of 16 lanes = same j
        q += __shfl_xor_sync(0xffffffffu, q, o);
    float v = s * (q / (1.f + q)) * rsqrtf(q + EPS_);
    out[b * JD_ + t] = v;
}

// ---------------------------------------------------------------------------
extern "C" void kernel_launch(void* const* d_in, const int* in_sizes, int n_in,
                              void* d_out, int out_size) {
    const float* x = (const float*)d_in[0];
    const float* w = (const float*)d_in[1];
    if (in_sizes[0] != B_ * N_ * E_) {       // defensive input-order check
        x = (const float*)d_in[1];
        w = (const float*)d_in[0];
    }

    k_zero<<<96, 1024>>>();
    k_u<<<N_, 256>>>(x, w);

    dim3 pg(16, B_);
    k_pass<<<pg, 256>>>(-1, 0);              // iteration 1: uniform c -> s1
    k_squash_j<<<B_, JD_>>>(0, 0);           // v1 = squash_J(s1)
    k_pass<<<pg, 256>>>(0, 1);               // iteration 2: c=softmax(u.v1) -> s2
    k_squash_j<<<B_, JD_>>>(1, 1);           // vsum = squash_J(s2) + v1
    k_pass<<<pg, 256>>>(1, 2);               // final: c=softmax(u.vsum) -> s3
    k_final<<<B_, JD_>>>((float*)d_out);     // out = squash_D(s3)
}